// round 16
// baseline (speedup 1.0000x reference)
#include <cuda_runtime.h>
#include <cuda_fp16.h>
#include <cstdint>

// ============================================================================
// Attention: softmax(Q K^T) V, B=4 H=16 S=2048 D=64, fp32 in/out.
// FA2-style mma.sync kernel. S = (Qhi + Qlo) · fp16(K)^T (rel_err ~8e-4).
// K/V pre-converted once into pre-swizzled fp16 tiles (scratch); loop
// cp.asyncs ready tiles (double-buffered). ex2.f16x2 softmax, MMA row-sums.
// R13: TN 64->128 (NIT 16) — halves per-iter fixed costs (barriers, shfl
// chains, waits, rescales) per unit of tensor work; ballot-skips O-rescale
// when the running max didn't advance. 2 CTAs/SM.
// ============================================================================

#define DINLINE __device__ __forceinline__

static constexpr int S_LEN = 2048;
static constexpr int HDIM  = 64;
static constexpr int TM    = 64;           // Q rows per CTA
static constexpr int TN    = 128;          // K/V rows per iteration
static constexpr int NIT   = S_LEN / TN;   // 16
static constexpr int NTHREADS = 128;       // 4 warps
static constexpr int NQT   = S_LEN / TM;   // 32 Q tiles per head
static constexpr int NHEADS = 64;
static constexpr int TILE_BYTES = 64 * 128;          // 8192 per 64-row tile
static constexpr int NTILES = NHEADS * (S_LEN / 64); // 2048
static constexpr uint32_t ONES2 = 0x3C003C00u;       // half2(1,1)

// scratch: pre-swizzled fp16 tiles (K, V), 16 MB each
__device__ __align__(16) uint8_t d_kh[(size_t)NTILES * TILE_BYTES];
__device__ __align__(16) uint8_t d_vh[(size_t)NTILES * TILE_BYTES];

// main-kernel dynamic SMEM layout (bytes)
static constexpr int SM_QH = 0;            // 64 x 64 fp16 SW128 (8 KB)
static constexpr int SM_QL = 8192;         // 64 x 64 fp16 SW128 (8 KB)
static constexpr int SM_ST = 16384;        // 2 stages x (K 16K | V 16K)
static constexpr int STAGE = 32768;
static constexpr int ST_V  = 16384;
static constexpr int SMEM_BYTES = SM_ST + 2 * STAGE;   // 80 KB

// ---------------------------------------------------------------------------
DINLINE uint32_t smem_u32(const void* p) {
    uint32_t a;
    asm("{ .reg .u64 t; cvta.to.shared.u64 t, %1; cvt.u32.u64 %0, t; }" : "=r"(a) : "l"(p));
    return a;
}

DINLINE float ex2f(float x) {
    float y;
    asm("ex2.approx.ftz.f32 %0, %1;" : "=f"(y) : "f"(x));
    return y;
}

// packed fp16 exp2: one MUFU op for two values
DINLINE uint32_t ex2h2(uint32_t a) {
    uint32_t y;
    asm("ex2.approx.f16x2 %0, %1;" : "=r"(y) : "r"(a));
    return y;
}

DINLINE uint32_t h2_bits(__half2 h) {
    uint32_t u;
    __builtin_memcpy(&u, &h, 4);
    return u;
}

DINLINE uint32_t sw_off(int row, int colb) {
    uint32_t off = (uint32_t)(row * 128 + colb);
    return off ^ ((off >> 3) & 0x70);
}

DINLINE uint32_t sw_addr(uint32_t base, int row, int colb) {
    return base + sw_off(row, colb);
}

DINLINE void ldmatrix_x4(uint32_t* r, uint32_t addr) {
    asm volatile("ldmatrix.sync.aligned.m8n8.x4.shared.b16 {%0,%1,%2,%3}, [%4];"
                 : "=r"(r[0]), "=r"(r[1]), "=r"(r[2]), "=r"(r[3]) : "r"(addr));
}

DINLINE void ldmatrix_x4_trans(uint32_t* r, uint32_t addr) {
    asm volatile("ldmatrix.sync.aligned.m8n8.x4.trans.shared.b16 {%0,%1,%2,%3}, [%4];"
                 : "=r"(r[0]), "=r"(r[1]), "=r"(r[2]), "=r"(r[3]) : "r"(addr));
}

DINLINE void mma_16816(float* c, const uint32_t* a, uint32_t b0, uint32_t b1) {
    asm volatile(
        "mma.sync.aligned.m16n8k16.row.col.f32.f16.f16.f32 "
        "{%0,%1,%2,%3}, {%4,%5,%6,%7}, {%8,%9}, {%0,%1,%2,%3};"
        : "+f"(c[0]), "+f"(c[1]), "+f"(c[2]), "+f"(c[3])
        : "r"(a[0]), "r"(a[1]), "r"(a[2]), "r"(a[3]), "r"(b0), "r"(b1));
}

DINLINE void sts_v2(uint32_t addr, uint32_t x, uint32_t y) {
    asm volatile("st.shared.v2.b32 [%0], {%1, %2};" :: "r"(addr), "r"(x), "r"(y) : "memory");
}

// Split-precision pack: hi = fp16(x), lo = fp16(x - hi)
DINLINE void split2(float x, float y, uint32_t& hi, uint32_t& lo) {
    __half hx = __float2half_rn(x);
    __half hy = __float2half_rn(y);
    __half lx = __float2half_rn(x - __half2float(hx));
    __half ly = __float2half_rn(y - __half2float(hy));
    hi = h2_bits(__halves2half2(hx, hy));
    lo = h2_bits(__halves2half2(lx, ly));
}

#define CP_COMMIT() asm volatile("cp.async.commit_group;" ::: "memory")
#define CP_WAIT0()  asm volatile("cp.async.wait_group 0;" ::: "memory")

// cp.async one pre-swizzled 16 KB block (two consecutive 8 KB scratch tiles).
DINLINE void cp_block16k(const uint8_t* __restrict__ g, uint32_t s) {
    const int t = threadIdx.x;
#pragma unroll
    for (int i = 0; i < 8; i++) {
        int idx = t + i * NTHREADS;
        asm volatile("cp.async.cg.shared.global [%0], [%1], 16;"
                     :: "r"(s + idx * 16), "l"(g + idx * 16) : "memory");
    }
}

// ---------------------------------------------------------------------------
// Pre-pass: K/V fp32 -> pre-swizzled fp16 tiles in scratch (64-row tiles).
// ---------------------------------------------------------------------------
__global__ void __launch_bounds__(256)
convert_kernel(const float* __restrict__ K, const float* __restrict__ V) {
    const int tile = blockIdx.x;
    const float* kg = K + (size_t)tile * (64 * HDIM);
    const float* vg = V + (size_t)tile * (64 * HDIM);
    uint8_t* okh = d_kh + (size_t)tile * TILE_BYTES;
    uint8_t* ovh = d_vh + (size_t)tile * TILE_BYTES;
    const int t = threadIdx.x;
#pragma unroll
    for (int i = 0; i < 4; i++) {
        int idx = t + i * 256;                 // float4 index, 0..1023
        int row = idx >> 4, c4 = idx & 15;
        uint32_t off = sw_off(row, c4 * 8);
        float4 kv = *reinterpret_cast<const float4*>(kg + idx * 4);
        *reinterpret_cast<uint2*>(okh + off) =
            make_uint2(h2_bits(__floats2half2_rn(kv.x, kv.y)),
                       h2_bits(__floats2half2_rn(kv.z, kv.w)));
        float4 vv = *reinterpret_cast<const float4*>(vg + idx * 4);
        *reinterpret_cast<uint2*>(ovh + off) =
            make_uint2(h2_bits(__floats2half2_rn(vv.x, vv.y)),
                       h2_bits(__floats2half2_rn(vv.z, vv.w)));
    }
}

// Q: direct gmem load -> split fp16 tiles (once per CTA, 64 rows)
DINLINE void load_q_split(const float* __restrict__ g, uint32_t shi, uint32_t slo) {
    const int t = threadIdx.x;
    const float scale = 1.4426950408889634f;   // log2(e)
#pragma unroll
    for (int i = 0; i < 8; i++) {
        int idx = t + i * NTHREADS;            // 0..1023 float4s (64 rows x 16)
        int row = idx >> 4, c4 = idx & 15;
        float4 v = *reinterpret_cast<const float4*>(g + row * HDIM + c4 * 4);
        uint32_t h0, l0, h1, l1;
        split2(v.x * scale, v.y * scale, h0, l0);
        split2(v.z * scale, v.w * scale, h1, l1);
        sts_v2(sw_addr(shi, row, c4 * 8), h0, h1);
        sts_v2(sw_addr(slo, row, c4 * 8), l0, l1);
    }
}

// ---------------------------------------------------------------------------
__global__ void __launch_bounds__(NTHREADS, 2)
attn_kernel(const float* __restrict__ Q, float* __restrict__ Out) {
    extern __shared__ char smem[];
    const uint32_t sb = smem_u32(smem);

    const int tid = threadIdx.x;
    const int w   = tid >> 5;        // 0..3
    const int lid = tid & 31;
    const int g   = lid >> 2;
    const int tig = lid & 3;

    const int bh = blockIdx.x >> 5;          // head (64)
    const int qt = blockIdx.x & 31;          // Q tile of 64 rows (32)
    const size_t head_off = (size_t)bh * S_LEN * HDIM;
    const float* qg = Q + head_off + (size_t)qt * TM * HDIM;
    float* og = Out + head_off + (size_t)qt * TM * HDIM;
    const size_t tbase = (size_t)bh * (S_LEN / 64);  // first 64-row tile of head

    // ---- prologue: prefetch block 0 (2 tiles), stage Q, build Q frags ----
    cp_block16k(d_kh + tbase * TILE_BYTES, sb + SM_ST);
    cp_block16k(d_vh + tbase * TILE_BYTES, sb + SM_ST + ST_V);
    CP_COMMIT();

    load_q_split(qg, sb + SM_QH, sb + SM_QL);
    __syncthreads();

    uint32_t qh[4][4], ql[4][4];
    {
        const int r   = lid & 7;
        const int sel = lid >> 3;
        const int row = 16 * w + (sel & 1) * 8 + r;
#pragma unroll
        for (int kb = 0; kb < 4; kb++) {
            int colb = kb * 32 + (sel >> 1) * 16;
            ldmatrix_x4(qh[kb], sw_addr(sb + SM_QH, row, colb));
            ldmatrix_x4(ql[kb], sw_addr(sb + SM_QL, row, colb));
        }
    }

    float oacc[8][4];
#pragma unroll
    for (int nb = 0; nb < 8; nb++)
#pragma unroll
        for (int i = 0; i < 4; i++) oacc[nb][i] = 0.f;

    float m0 = -__int_as_float(0x7f800000), m1 = m0;
    float l0 = 0.f, l1 = 0.f;

    const int lr   = lid & 7;
    const int lsel = lid >> 3;

    for (int j = 0; j < NIT; j++) {
        const uint32_t st = sb + SM_ST + (j & 1) * STAGE;

        // block j arrived; all warps done reading the other stage (iter j-1)
        CP_WAIT0();
        __syncthreads();

        // prefetch block j+1 into the other stage (overlaps all MMAs below)
        if (j + 1 < NIT) {
            const uint32_t stn = sb + SM_ST + ((j + 1) & 1) * STAGE;
            const size_t toff = (tbase + 2 * (j + 1)) * TILE_BYTES;
            cp_block16k(d_kh + toff, stn);
            cp_block16k(d_vh + toff, stn + ST_V);
            CP_COMMIT();
        }

        // ---- S = (Qhi + Qlo) Khi^T : 16 x 128 per warp, 128 MMAs ----
        float sacc[16][4];
#pragma unroll
        for (int nb = 0; nb < 16; nb++) {
#pragma unroll
            for (int i = 0; i < 4; i++) sacc[nb][i] = 0.f;
#pragma unroll
            for (int kbp = 0; kbp < 2; kbp++) {
                uint32_t kh[4];
                int colb = 64 * kbp + lsel * 16;
                ldmatrix_x4(kh, sw_addr(st, 8 * nb + lr, colb));
                mma_16816(sacc[nb], qh[2 * kbp],     kh[0], kh[1]);
                mma_16816(sacc[nb], qh[2 * kbp + 1], kh[2], kh[3]);
                mma_16816(sacc[nb], ql[2 * kbp],     kh[0], kh[1]);
                mma_16816(sacc[nb], ql[2 * kbp + 1], kh[2], kh[3]);
            }
        }

        // ---- online softmax: row max (fp32) ----
        float mr0 = sacc[0][0], mr1 = sacc[0][2];
#pragma unroll
        for (int nb = 0; nb < 16; nb++) {
            mr0 = fmaxf(mr0, fmaxf(sacc[nb][0], sacc[nb][1]));
            mr1 = fmaxf(mr1, fmaxf(sacc[nb][2], sacc[nb][3]));
        }
        mr0 = fmaxf(mr0, __shfl_xor_sync(0xffffffffu, mr0, 1));
        mr0 = fmaxf(mr0, __shfl_xor_sync(0xffffffffu, mr0, 2));
        mr1 = fmaxf(mr1, __shfl_xor_sync(0xffffffffu, mr1, 1));
        mr1 = fmaxf(mr1, __shfl_xor_sync(0xffffffffu, mr1, 2));

        float mn0 = fmaxf(m0, mr0), mn1 = fmaxf(m1, mr1);
        float al0 = ex2f(m0 - mn0), al1 = ex2f(m1 - mn1);
        m0 = mn0; m1 = mn1;

        // ---- P = exp2(s - mn) directly in packed fp16 (A-fragments) ----
        uint32_t pa[8][4];
#pragma unroll
        for (int kb2 = 0; kb2 < 8; kb2++) {
            pa[kb2][0] = ex2h2(h2_bits(__floats2half2_rn(sacc[2 * kb2][0] - mn0,
                                                         sacc[2 * kb2][1] - mn0)));
            pa[kb2][1] = ex2h2(h2_bits(__floats2half2_rn(sacc[2 * kb2][2] - mn1,
                                                         sacc[2 * kb2][3] - mn1)));
            pa[kb2][2] = ex2h2(h2_bits(__floats2half2_rn(sacc[2 * kb2 + 1][0] - mn0,
                                                         sacc[2 * kb2 + 1][1] - mn0)));
            pa[kb2][3] = ex2h2(h2_bits(__floats2half2_rn(sacc[2 * kb2 + 1][2] - mn1,
                                                         sacc[2 * kb2 + 1][3] - mn1)));
        }

        // ---- row sums via MMA against ones (fp32 accum of actual fp16 P) ----
        float sumacc[4] = {0.f, 0.f, 0.f, 0.f};
#pragma unroll
        for (int kb2 = 0; kb2 < 8; kb2++)
            mma_16816(sumacc, pa[kb2], ONES2, ONES2);
        l0 = l0 * al0 + sumacc[0];
        l1 = l1 * al1 + sumacc[2];

        // ---- rescale O accum (skip when max didn't advance anywhere) ----
        if (__ballot_sync(0xffffffffu, (al0 != 1.f) | (al1 != 1.f))) {
#pragma unroll
            for (int nb = 0; nb < 8; nb++) {
                oacc[nb][0] *= al0; oacc[nb][1] *= al0;
                oacc[nb][2] *= al1; oacc[nb][3] *= al1;
            }
        }

        // ---- O += P V (K-dim 128 over seq) ----
#pragma unroll
        for (int nbp = 0; nbp < 4; nbp++) {
#pragma unroll
            for (int kb2 = 0; kb2 < 8; kb2++) {
                uint32_t vf[4];
                int row  = 16 * kb2 + (lsel & 1) * 8 + lr;
                int colb = 16 * (2 * nbp + (lsel >> 1));
                ldmatrix_x4_trans(vf, sw_addr(st + ST_V, row, colb));
                mma_16816(oacc[2 * nbp],     pa[kb2], vf[0], vf[1]);
                mma_16816(oacc[2 * nbp + 1], pa[kb2], vf[2], vf[3]);
            }
        }
        // no trailing sync: next iter's entry sync protects stage reuse
    }

    // ---- epilogue: O / l -> gmem ----
    float inv0 = __fdividef(1.f, l0);
    float inv1 = __fdividef(1.f, l1);
    const int row0 = 16 * w + g;
    const int row1 = row0 + 8;
#pragma unroll
    for (int nb = 0; nb < 8; nb++) {
        int col = 8 * nb + 2 * tig;
        *reinterpret_cast<float2*>(og + (size_t)row0 * HDIM + col) =
            make_float2(oacc[nb][0] * inv0, oacc[nb][1] * inv0);
        *reinterpret_cast<float2*>(og + (size_t)row1 * HDIM + col) =
            make_float2(oacc[nb][2] * inv1, oacc[nb][3] * inv1);
    }
}

// ---------------------------------------------------------------------------
extern "C" void kernel_launch(void* const* d_in, const int* in_sizes, int n_in,
                              void* d_out, int out_size) {
    const float* Q = (const float*)d_in[0];
    const float* K = (const float*)d_in[1];
    const float* V = (const float*)d_in[2];
    float* O = (float*)d_out;

    cudaFuncSetAttribute(attn_kernel, cudaFuncAttributeMaxDynamicSharedMemorySize, SMEM_BYTES);

    convert_kernel<<<NTILES, 256>>>(K, V);            // ~15 us pre-pass
    attn_kernel<<<64 * NQT, NTHREADS, SMEM_BYTES>>>(Q, O);
}

// round 17
// speedup vs baseline: 1.6037x; 1.6037x over previous
#include <cuda_runtime.h>
#include <cuda_fp16.h>
#include <cstdint>

// ============================================================================
// Attention: softmax(Q K^T) V, B=4 H=16 S=2048 D=64, fp32 in/out.
// FA2-style mma.sync kernel. S = (Qhi + Qlo) · fp16(K)^T (rel_err ~8e-4).
// K/V pre-converted once into pre-swizzled fp16 tiles (scratch); loop
// cp.asyncs ready tiles (double-buffered). ex2.f16x2 softmax, MMA row-sums.
// 3 CTAs/SM. R14 (after R13 reg-spill regression, reverted to R12 shape):
//   - packed-fp16 max shfl reduction (2 shfls instead of 4; mn rounding
//     cancels exactly in P/l normalization)
//   - ballot-skip O-rescale when the running max didn't advance
//   - ones-MMA row-sum moved after PV (off the critical path)
// ============================================================================

#define DINLINE __device__ __forceinline__

static constexpr int S_LEN = 2048;
static constexpr int HDIM  = 64;
static constexpr int TM    = 64;           // Q rows per CTA
static constexpr int TN    = 64;           // K/V rows per iteration
static constexpr int NIT   = S_LEN / TN;   // 32
static constexpr int NTHREADS = 128;       // 4 warps
static constexpr int NQT   = S_LEN / TM;   // 32 Q tiles per head
static constexpr int NHEADS = 64;
static constexpr int TILE_BYTES = TN * 128;          // 8192 (64 rows x 128B)
static constexpr int NTILES = NHEADS * NIT;          // 2048
static constexpr uint32_t ONES2 = 0x3C003C00u;       // half2(1,1)

// scratch: pre-swizzled fp16 tiles (K, V), 16 MB each
__device__ __align__(16) uint8_t d_kh[(size_t)NTILES * TILE_BYTES];
__device__ __align__(16) uint8_t d_vh[(size_t)NTILES * TILE_BYTES];

// main-kernel dynamic SMEM layout (bytes)
static constexpr int SM_QH = 0;            // 64 x 64 fp16 SW128 (8 KB)
static constexpr int SM_QL = 8192;         // 64 x 64 fp16 SW128 (8 KB)
static constexpr int SM_ST = 16384;        // 2 stages x (K 8K | V 8K)
static constexpr int STAGE = 16384;
static constexpr int ST_V  = 8192;
static constexpr int SMEM_BYTES = SM_ST + 2 * STAGE;   // 48 KB

// ---------------------------------------------------------------------------
DINLINE uint32_t smem_u32(const void* p) {
    uint32_t a;
    asm("{ .reg .u64 t; cvta.to.shared.u64 t, %1; cvt.u32.u64 %0, t; }" : "=r"(a) : "l"(p));
    return a;
}

DINLINE float ex2f(float x) {
    float y;
    asm("ex2.approx.ftz.f32 %0, %1;" : "=f"(y) : "f"(x));
    return y;
}

// packed fp16 exp2: one MUFU op for two values
DINLINE uint32_t ex2h2(uint32_t a) {
    uint32_t y;
    asm("ex2.approx.f16x2 %0, %1;" : "=r"(y) : "r"(a));
    return y;
}

DINLINE uint32_t h2_bits(__half2 h) {
    uint32_t u;
    __builtin_memcpy(&u, &h, 4);
    return u;
}

DINLINE __half2 bits_h2(uint32_t u) {
    __half2 h;
    __builtin_memcpy(&h, &u, 4);
    return h;
}

DINLINE uint32_t sw_off(int row, int colb) {
    uint32_t off = (uint32_t)(row * 128 + colb);
    return off ^ ((off >> 3) & 0x70);
}

DINLINE uint32_t sw_addr(uint32_t base, int row, int colb) {
    return base + sw_off(row, colb);
}

DINLINE void ldmatrix_x4(uint32_t* r, uint32_t addr) {
    asm volatile("ldmatrix.sync.aligned.m8n8.x4.shared.b16 {%0,%1,%2,%3}, [%4];"
                 : "=r"(r[0]), "=r"(r[1]), "=r"(r[2]), "=r"(r[3]) : "r"(addr));
}

DINLINE void ldmatrix_x4_trans(uint32_t* r, uint32_t addr) {
    asm volatile("ldmatrix.sync.aligned.m8n8.x4.trans.shared.b16 {%0,%1,%2,%3}, [%4];"
                 : "=r"(r[0]), "=r"(r[1]), "=r"(r[2]), "=r"(r[3]) : "r"(addr));
}

DINLINE void mma_16816(float* c, const uint32_t* a, uint32_t b0, uint32_t b1) {
    asm volatile(
        "mma.sync.aligned.m16n8k16.row.col.f32.f16.f16.f32 "
        "{%0,%1,%2,%3}, {%4,%5,%6,%7}, {%8,%9}, {%0,%1,%2,%3};"
        : "+f"(c[0]), "+f"(c[1]), "+f"(c[2]), "+f"(c[3])
        : "r"(a[0]), "r"(a[1]), "r"(a[2]), "r"(a[3]), "r"(b0), "r"(b1));
}

DINLINE void sts_v2(uint32_t addr, uint32_t x, uint32_t y) {
    asm volatile("st.shared.v2.b32 [%0], {%1, %2};" :: "r"(addr), "r"(x), "r"(y) : "memory");
}

// Split-precision pack: hi = fp16(x), lo = fp16(x - hi)
DINLINE void split2(float x, float y, uint32_t& hi, uint32_t& lo) {
    __half hx = __float2half_rn(x);
    __half hy = __float2half_rn(y);
    __half lx = __float2half_rn(x - __half2float(hx));
    __half ly = __float2half_rn(y - __half2float(hy));
    hi = h2_bits(__halves2half2(hx, hy));
    lo = h2_bits(__halves2half2(lx, ly));
}

#define CP_COMMIT() asm volatile("cp.async.commit_group;" ::: "memory")
#define CP_WAIT0()  asm volatile("cp.async.wait_group 0;" ::: "memory")

// cp.async one pre-swizzled 8 KB tile (global scratch -> smem). 4 x 16B/thread.
DINLINE void cp_tile(const uint8_t* __restrict__ g, uint32_t s) {
    const int t = threadIdx.x;
#pragma unroll
    for (int i = 0; i < 4; i++) {
        int idx = t + i * NTHREADS;
        asm volatile("cp.async.cg.shared.global [%0], [%1], 16;"
                     :: "r"(s + idx * 16), "l"(g + idx * 16) : "memory");
    }
}

// ---------------------------------------------------------------------------
// Pre-pass: K/V fp32 -> pre-swizzled fp16 tiles in scratch.
// ---------------------------------------------------------------------------
__global__ void __launch_bounds__(256)
convert_kernel(const float* __restrict__ K, const float* __restrict__ V) {
    const int tile = blockIdx.x;
    const float* kg = K + (size_t)tile * (TN * HDIM);
    const float* vg = V + (size_t)tile * (TN * HDIM);
    uint8_t* okh = d_kh + (size_t)tile * TILE_BYTES;
    uint8_t* ovh = d_vh + (size_t)tile * TILE_BYTES;
    const int t = threadIdx.x;
#pragma unroll
    for (int i = 0; i < 4; i++) {
        int idx = t + i * 256;                 // float4 index, 0..1023
        int row = idx >> 4, c4 = idx & 15;
        uint32_t off = sw_off(row, c4 * 8);
        float4 kv = *reinterpret_cast<const float4*>(kg + idx * 4);
        *reinterpret_cast<uint2*>(okh + off) =
            make_uint2(h2_bits(__floats2half2_rn(kv.x, kv.y)),
                       h2_bits(__floats2half2_rn(kv.z, kv.w)));
        float4 vv = *reinterpret_cast<const float4*>(vg + idx * 4);
        *reinterpret_cast<uint2*>(ovh + off) =
            make_uint2(h2_bits(__floats2half2_rn(vv.x, vv.y)),
                       h2_bits(__floats2half2_rn(vv.z, vv.w)));
    }
}

// Q: direct gmem load -> split fp16 tiles (once per CTA, 64 rows)
DINLINE void load_q_split(const float* __restrict__ g, uint32_t shi, uint32_t slo) {
    const int t = threadIdx.x;
    const float scale = 1.4426950408889634f;   // log2(e)
#pragma unroll
    for (int i = 0; i < 8; i++) {
        int idx = t + i * NTHREADS;            // 0..1023 float4s (64 rows x 16)
        int row = idx >> 4, c4 = idx & 15;
        float4 v = *reinterpret_cast<const float4*>(g + row * HDIM + c4 * 4);
        uint32_t h0, l0, h1, l1;
        split2(v.x * scale, v.y * scale, h0, l0);
        split2(v.z * scale, v.w * scale, h1, l1);
        sts_v2(sw_addr(shi, row, c4 * 8), h0, h1);
        sts_v2(sw_addr(slo, row, c4 * 8), l0, l1);
    }
}

// ---------------------------------------------------------------------------
__global__ void __launch_bounds__(NTHREADS, 3)
attn_kernel(const float* __restrict__ Q, float* __restrict__ Out) {
    extern __shared__ char smem[];
    const uint32_t sb = smem_u32(smem);

    const int tid = threadIdx.x;
    const int w   = tid >> 5;        // 0..3
    const int lid = tid & 31;
    const int g   = lid >> 2;
    const int tig = lid & 3;

    const int bh = blockIdx.x >> 5;          // head (64)
    const int qt = blockIdx.x & 31;          // Q tile of 64 rows (32)
    const size_t head_off = (size_t)bh * S_LEN * HDIM;
    const float* qg = Q + head_off + (size_t)qt * TM * HDIM;
    float* og = Out + head_off + (size_t)qt * TM * HDIM;
    const size_t tbase = (size_t)bh * NIT;   // first K/V tile of this head

    // ---- prologue: prefetch tile 0, stage Q, build Q frags ----
    cp_tile(d_kh + tbase * TILE_BYTES, sb + SM_ST);
    cp_tile(d_vh + tbase * TILE_BYTES, sb + SM_ST + ST_V);
    CP_COMMIT();

    load_q_split(qg, sb + SM_QH, sb + SM_QL);
    __syncthreads();

    uint32_t qh[4][4], ql[4][4];
    {
        const int r   = lid & 7;
        const int sel = lid >> 3;
        const int row = 16 * w + (sel & 1) * 8 + r;
#pragma unroll
        for (int kb = 0; kb < 4; kb++) {
            int colb = kb * 32 + (sel >> 1) * 16;
            ldmatrix_x4(qh[kb], sw_addr(sb + SM_QH, row, colb));
            ldmatrix_x4(ql[kb], sw_addr(sb + SM_QL, row, colb));
        }
    }

    float oacc[8][4];
#pragma unroll
    for (int nb = 0; nb < 8; nb++)
#pragma unroll
        for (int i = 0; i < 4; i++) oacc[nb][i] = 0.f;

    float m0 = -__int_as_float(0x7f800000), m1 = m0;
    float l0 = 0.f, l1 = 0.f;

    const int lr   = lid & 7;
    const int lsel = lid >> 3;

    for (int j = 0; j < NIT; j++) {
        const uint32_t st = sb + SM_ST + (j & 1) * STAGE;

        // tile j arrived; all warps done reading the other stage (iter j-1)
        CP_WAIT0();
        __syncthreads();

        // prefetch tile j+1 into the other stage (overlaps all MMAs below)
        if (j + 1 < NIT) {
            const uint32_t stn = sb + SM_ST + ((j + 1) & 1) * STAGE;
            const size_t toff = (tbase + j + 1) * TILE_BYTES;
            cp_tile(d_kh + toff, stn);
            cp_tile(d_vh + toff, stn + ST_V);
            CP_COMMIT();
        }

        // ---- S = (Qhi + Qlo) Khi^T : 16 x 64 per warp, 64 MMAs ----
        float sacc[8][4];
#pragma unroll
        for (int nb = 0; nb < 8; nb++) {
#pragma unroll
            for (int i = 0; i < 4; i++) sacc[nb][i] = 0.f;
#pragma unroll
            for (int kbp = 0; kbp < 2; kbp++) {
                uint32_t kh[4];
                int colb = 64 * kbp + lsel * 16;
                ldmatrix_x4(kh, sw_addr(st, 8 * nb + lr, colb));
                mma_16816(sacc[nb], qh[2 * kbp],     kh[0], kh[1]);
                mma_16816(sacc[nb], qh[2 * kbp + 1], kh[2], kh[3]);
                mma_16816(sacc[nb], ql[2 * kbp],     kh[0], kh[1]);
                mma_16816(sacc[nb], ql[2 * kbp + 1], kh[2], kh[3]);
            }
        }

        // ---- online softmax: local row max (fp32), packed fp16 shfl ----
        float mr0 = sacc[0][0], mr1 = sacc[0][2];
#pragma unroll
        for (int nb = 0; nb < 8; nb++) {
            mr0 = fmaxf(mr0, fmaxf(sacc[nb][0], sacc[nb][1]));
            mr1 = fmaxf(mr1, fmaxf(sacc[nb][2], sacc[nb][3]));
        }
        // pack both row-maxes; 2 shfls instead of 4. mn rounding to fp16 is
        // exact-cancelling in P/l (same factor on numerator and denominator).
        uint32_t mpk = h2_bits(__floats2half2_rn(mr0, mr1));
        mpk = h2_bits(__hmax2(bits_h2(mpk),
                              bits_h2(__shfl_xor_sync(0xffffffffu, mpk, 1))));
        mpk = h2_bits(__hmax2(bits_h2(mpk),
                              bits_h2(__shfl_xor_sync(0xffffffffu, mpk, 2))));
        __half2 mh = bits_h2(mpk);
        float mt0 = __low2float(mh), mt1 = __high2float(mh);

        float mn0 = fmaxf(m0, mt0), mn1 = fmaxf(m1, mt1);
        float al0 = ex2f(m0 - mn0), al1 = ex2f(m1 - mn1);
        m0 = mn0; m1 = mn1;

        // ---- P = exp2(s - mn) directly in packed fp16 (A-fragments) ----
        uint32_t pa[4][4];
#pragma unroll
        for (int kb2 = 0; kb2 < 4; kb2++) {
            pa[kb2][0] = ex2h2(h2_bits(__floats2half2_rn(sacc[2 * kb2][0] - mn0,
                                                         sacc[2 * kb2][1] - mn0)));
            pa[kb2][1] = ex2h2(h2_bits(__floats2half2_rn(sacc[2 * kb2][2] - mn1,
                                                         sacc[2 * kb2][3] - mn1)));
            pa[kb2][2] = ex2h2(h2_bits(__floats2half2_rn(sacc[2 * kb2 + 1][0] - mn0,
                                                         sacc[2 * kb2 + 1][1] - mn0)));
            pa[kb2][3] = ex2h2(h2_bits(__floats2half2_rn(sacc[2 * kb2 + 1][2] - mn1,
                                                         sacc[2 * kb2 + 1][3] - mn1)));
        }

        // ---- rescale O accum (skip when max didn't advance anywhere) ----
        if (__ballot_sync(0xffffffffu, (al0 != 1.f) | (al1 != 1.f))) {
#pragma unroll
            for (int nb = 0; nb < 8; nb++) {
                oacc[nb][0] *= al0; oacc[nb][1] *= al0;
                oacc[nb][2] *= al1; oacc[nb][3] *= al1;
            }
        }

        // ---- O += P V ----
#pragma unroll
        for (int nbp = 0; nbp < 4; nbp++) {
#pragma unroll
            for (int kb2 = 0; kb2 < 4; kb2++) {
                uint32_t vf[4];
                int row  = 16 * kb2 + (lsel & 1) * 8 + lr;
                int colb = 16 * (2 * nbp + (lsel >> 1));
                ldmatrix_x4_trans(vf, sw_addr(st + ST_V, row, colb));
                mma_16816(oacc[2 * nbp],     pa[kb2], vf[0], vf[1]);
                mma_16816(oacc[2 * nbp + 1], pa[kb2], vf[2], vf[3]);
            }
        }

        // ---- row sums via MMA against ones (off the PV critical path) ----
        float sumacc[4] = {0.f, 0.f, 0.f, 0.f};
#pragma unroll
        for (int kb2 = 0; kb2 < 4; kb2++)
            mma_16816(sumacc, pa[kb2], ONES2, ONES2);
        l0 = l0 * al0 + sumacc[0];
        l1 = l1 * al1 + sumacc[2];
        // no trailing sync: next iter's entry sync protects stage reuse
    }

    // ---- epilogue: O / l -> gmem ----
    float inv0 = __fdividef(1.f, l0);
    float inv1 = __fdividef(1.f, l1);
    const int row0 = 16 * w + g;
    const int row1 = row0 + 8;
#pragma unroll
    for (int nb = 0; nb < 8; nb++) {
        int col = 8 * nb + 2 * tig;
        *reinterpret_cast<float2*>(og + (size_t)row0 * HDIM + col) =
            make_float2(oacc[nb][0] * inv0, oacc[nb][1] * inv0);
        *reinterpret_cast<float2*>(og + (size_t)row1 * HDIM + col) =
            make_float2(oacc[nb][2] * inv1, oacc[nb][3] * inv1);
    }
}

// ---------------------------------------------------------------------------
extern "C" void kernel_launch(void* const* d_in, const int* in_sizes, int n_in,
                              void* d_out, int out_size) {
    const float* Q = (const float*)d_in[0];
    const float* K = (const float*)d_in[1];
    const float* V = (const float*)d_in[2];
    float* O = (float*)d_out;

    cudaFuncSetAttribute(attn_kernel, cudaFuncAttributeMaxDynamicSharedMemorySize, SMEM_BYTES);

    convert_kernel<<<NTILES, 256>>>(K, V);            // ~15 us pre-pass
    attn_kernel<<<64 * NQT, NTHREADS, SMEM_BYTES>>>(Q, O);
}